// round 4
// baseline (speedup 1.0000x reference)
#include <cuda_runtime.h>

#define HD 64
#define NG 16
#define TILE 32
#define ETILE 64
#define APAD 34
#define SST 68          // smem stride (floats) for mma tiles: conflict-free
#define LN_EPS 1e-3f
#define NMAX 100000

typedef unsigned long long u64;
typedef unsigned int uint;

// persistent scratch (device globals; allocation is forbidden)
__device__ float g_h[NMAX * HD];
__device__ float g_P[NMAX * HD];
__device__ float g_pool[NMAX * HD];
__device__ float g_ctx[NG * HD];

// ---------------- fp32 f32x2 SIMT GEMM (node-side kernels) ----------------
__device__ __forceinline__ u64 dup2(float x) {
    u64 r; unsigned xi = __float_as_uint(x);
    asm("mov.b64 %0, {%1, %1};" : "=l"(r) : "r"(xi));
    return r;
}
__device__ __forceinline__ float2 unpack2(u64 v) {
    unsigned lo, hi;
    asm("mov.b64 {%0, %1}, %2;" : "=r"(lo), "=r"(hi) : "l"(v));
    return make_float2(__uint_as_float(lo), __uint_as_float(hi));
}
__device__ __forceinline__ void ffma2(u64& d, u64 a, u64 b) {
    asm("fma.rn.f32x2 %0, %1, %2, %0;" : "+l"(d) : "l"(a), "l"(b));
}
__device__ __forceinline__ void redv4(float* p, float4 v) {
    asm volatile("red.global.add.v4.f32 [%0], {%1,%2,%3,%4};"
                 :: "l"(p), "f"(v.x), "f"(v.y), "f"(v.z), "f"(v.w) : "memory");
}
__device__ __forceinline__ uint to_tf32(float f) {
    uint r; asm("cvt.rna.tf32.f32 %0, %1;" : "=r"(r) : "f"(f));
    return r;
}
__device__ __forceinline__ void mma_tf32(float c[4], uint a0, uint a1, uint a2, uint a3,
                                         uint b0, uint b1) {
    asm("mma.sync.aligned.m16n8k8.row.col.f32.tf32.tf32.f32 "
        "{%0,%1,%2,%3}, {%4,%5,%6,%7}, {%8,%9}, {%0,%1,%2,%3};"
        : "+f"(c[0]), "+f"(c[1]), "+f"(c[2]), "+f"(c[3])
        : "r"(a0), "r"(a1), "r"(a2), "r"(a3), "r"(b0), "r"(b1));
}

__device__ __forceinline__ void stage_w(const float* __restrict__ W, float* sW) {
    int t = threadIdx.x;
    float4* d4 = (float4*)sW;
    const float4* s4 = (const float4*)W;
#pragma unroll
    for (int i = 0; i < 8; i++) d4[t + i * 128] = s4[t + i * 128];
}
__device__ __forceinline__ void stage_xT(const float* __restrict__ X, float* sA, int valid) {
    int t = threadIdx.x;
#pragma unroll
    for (int i = 0; i < 4; i++) {
        int flat = 4 * t + 512 * i;
        int r = flat >> 6, k = flat & 63;
        float4 v = make_float4(0.f, 0.f, 0.f, 0.f);
        if (r < valid) v = *(const float4*)(X + flat);
        sA[(k + 0) * APAD + r] = v.x;
        sA[(k + 1) * APAD + r] = v.y;
        sA[(k + 2) * APAD + r] = v.z;
        sA[(k + 3) * APAD + r] = v.w;
    }
}
__device__ __forceinline__ void gemm_tile(const float* sA, const float* sW,
                                          int e0, int f0, u64 acc[2][4]) {
    const float* pA = sA + e0;
    const float* pW = sW + f0;
#pragma unroll 8
    for (int k = 0; k < 64; k++) {
        u64 a01 = *(const u64*)(pA);
        u64 a23 = *(const u64*)(pA + 2);
        float4 w = *(const float4*)(pW);
        u64 w0 = dup2(w.x), w1 = dup2(w.y), w2 = dup2(w.z), w3 = dup2(w.w);
        ffma2(acc[0][0], a01, w0); ffma2(acc[1][0], a23, w0);
        ffma2(acc[0][1], a01, w1); ffma2(acc[1][1], a23, w1);
        ffma2(acc[0][2], a01, w2); ffma2(acc[1][2], a23, w2);
        ffma2(acc[0][3], a01, w3); ffma2(acc[1][3], a23, w3);
        pA += APAD; pW += 64;
    }
}
__device__ __forceinline__ void acc_to_rows(u64 acc[2][4], float v[4][4]) {
#pragma unroll
    for (int p = 0; p < 2; p++)
#pragma unroll
        for (int j = 0; j < 4; j++) {
            float2 u = unpack2(acc[p][j]);
            v[2 * p][j] = u.x;
            v[2 * p + 1][j] = u.y;
        }
}

// K1: P = h @ W1 + b ; zero pooled ; (optionally) zero ctx
__global__ __launch_bounds__(128) void k_initP(
    const float* __restrict__ hext, int use_gh,
    const float* __restrict__ W1, const float* __restrict__ b,
    int N, int zero_ctx)
{
    __shared__ float sA[HD * APAD];
    __shared__ float sW[HD * HD];
    const float* hsrc = use_gh ? g_h : hext;
    int t = threadIdx.x;
    int nb = blockIdx.x * TILE;
    stage_xT(hsrc + (size_t)nb * HD, sA, min(TILE, N - nb));
    stage_w(W1, sW);
    __syncthreads();
    int e0 = (t >> 4) * 4, f0 = (t & 15) * 4;
    u64 acc[2][4] = {};
    gemm_tile(sA, sW, e0, f0, acc);
    float v[4][4]; acc_to_rows(acc, v);
    float4 bv = *(const float4*)(b + f0);
#pragma unroll
    for (int i = 0; i < 4; i++) {
        int n = nb + e0 + i;
        if (n < N)
            *(float4*)(g_P + (size_t)n * HD + f0) =
                make_float4(v[i][0] + bv.x, v[i][1] + bv.y, v[i][2] + bv.z, v[i][3] + bv.w);
    }
#pragma unroll
    for (int i = 0; i < 4; i++) {
        int flat = 4 * (t + 128 * i);
        int r = flat >> 6;
        if (nb + r < N)
            *(float4*)(g_pool + (size_t)nb * HD + flat) = make_float4(0.f, 0.f, 0.f, 0.f);
    }
    if (zero_ctx && blockIdx.x == 0)
        for (int i = t; i < NG * HD; i += 128) g_ctx[i] = 0.f;
}

// K2 (tf32 tensor-core): msg = relu(P[src] + emb @ W2) ; pooled[tgt] += msg
// 128 threads = 4 warps; tile = 64 edges x 64 feats; K = 64.
// Epilogue widened: shfl-combine adjacent lanes' pairs -> one red.v4 per 4 floats.
__global__ __launch_bounds__(128) void k_edge_mma(
    const float* __restrict__ emb, const int* __restrict__ esrc,
    const int* __restrict__ etgt, const float* __restrict__ W2, int E)
{
    __shared__ uint sA[ETILE * SST];   // emb tile, row-major [edge][k], tf32
    __shared__ uint sW[HD * SST];      // W2 transposed [n][k], tf32
    __shared__ int sid[2 * ETILE];
    int t = threadIdx.x;
    long long eb = (long long)blockIdx.x * ETILE;

    if (t < ETILE) {
        long long e = eb + t;
        sid[t] = (e < E) ? esrc[e] : 0;
        sid[ETILE + t] = (e < E) ? etgt[e] : 0;
    }
    // stage emb (tf32) row-major, stride SST
#pragma unroll
    for (int i = 0; i < 8; i++) {
        int flat = 4 * t + 512 * i;
        int r = flat >> 6, k = flat & 63;
        float4 v = make_float4(0.f, 0.f, 0.f, 0.f);
        if (eb + r < E) v = *(const float4*)(emb + eb * HD + flat);
        uint4 c = make_uint4(to_tf32(v.x), to_tf32(v.y), to_tf32(v.z), to_tf32(v.w));
        *(uint4*)(sA + r * SST + k) = c;
    }
    // stage W2 transposed [n][k] (tf32)
#pragma unroll
    for (int i = 0; i < 8; i++) {
        int flat = 4 * t + 512 * i;
        int k = flat >> 6, n = flat & 63;
        float4 v = *(const float4*)(W2 + flat);
        sW[(n + 0) * SST + k] = to_tf32(v.x);
        sW[(n + 1) * SST + k] = to_tf32(v.y);
        sW[(n + 2) * SST + k] = to_tf32(v.z);
        sW[(n + 3) * SST + k] = to_tf32(v.w);
    }
    __syncthreads();

    int lane = t & 31;
    int gid4 = lane >> 2;   // group id 0..7
    int tig  = lane & 3;    // thread-in-group 0..3
    int r0 = (t >> 5) * 16; // warp's edge-row base

    float acc[8][4] = {};
    const uint* aRow0 = sA + (r0 + gid4) * SST;
    const uint* aRow1 = aRow0 + 8 * SST;
#pragma unroll
    for (int kk = 0; kk < 8; kk++) {
        int ca = kk * 8 + tig;
        uint a0 = aRow0[ca], a1 = aRow1[ca], a2 = aRow0[ca + 4], a3 = aRow1[ca + 4];
#pragma unroll
        for (int nt = 0; nt < 8; nt++) {
            const uint* bp = sW + (nt * 8 + gid4) * SST + ca;
            mma_tf32(acc[nt], a0, a1, a2, a3, bp[0], bp[4]);
        }
    }

    // epilogue: combine lane pairs -> float4, relu(P[src]+acc), one red.v4 per quad
#pragma unroll
    for (int p = 0; p < 2; p++) {
        int row = r0 + gid4 + 8 * p;
        int s = sid[row], g = sid[ETILE + row];
        bool owner = ((tig & 1) == 0) && (eb + row < E);
        const float* Ps = g_P + (size_t)s * HD;
        float* Pg = g_pool + (size_t)g * HD;
#pragma unroll
        for (int nt = 0; nt < 8; nt++) {
            float a0 = acc[nt][2 * p + 0];
            float a1 = acc[nt][2 * p + 1];
            // partner (tig^1) holds the adjacent column pair of the SAME row
            float b0 = __shfl_xor_sync(0xffffffffu, a0, 1);
            float b1 = __shfl_xor_sync(0xffffffffu, a1, 1);
            if (owner) {
                int col = nt * 8 + 2 * tig;  // tig in {0,2} -> quad base 0 / 4
                float4 pv = *(const float4*)(Ps + col);
                float4 m = make_float4(fmaxf(a0 + pv.x, 0.f), fmaxf(a1 + pv.y, 0.f),
                                       fmaxf(b0 + pv.z, 0.f), fmaxf(b1 + pv.w, 0.f));
                redv4(Pg + col, m);
            }
        }
    }
}

// K3: h = LayerNorm(relu(h + h@Wres[0:64] + pooled@Wres[64:128] + b))
__global__ __launch_bounds__(128) void k_node(
    const float* __restrict__ hext, int use_gh,
    const float* __restrict__ Wres, const float* __restrict__ bres,
    const float* __restrict__ gam, const float* __restrict__ bet, int N)
{
    __shared__ float sA[HD * APAD];
    __shared__ float sW[HD * HD];
    const float* hin = use_gh ? g_h : hext;
    int t = threadIdx.x;
    int nb = blockIdx.x * TILE;
    int valid = min(TILE, N - nb);
    int e0 = (t >> 4) * 4, f0 = (t & 15) * 4;
    u64 acc[2][4] = {};

    stage_xT(hin + (size_t)nb * HD, sA, valid);
    stage_w(Wres, sW);
    __syncthreads();
    gemm_tile(sA, sW, e0, f0, acc);
    __syncthreads();
    stage_xT(g_pool + (size_t)nb * HD, sA, valid);
    stage_w(Wres + 4096, sW);
    __syncthreads();
    gemm_tile(sA, sW, e0, f0, acc);

    float v[4][4]; acc_to_rows(acc, v);
    float4 bv = *(const float4*)(bres + f0);
    float4 gv = *(const float4*)(gam + f0);
    float4 btv = *(const float4*)(bet + f0);
#pragma unroll
    for (int i = 0; i < 4; i++) {
        int n = nb + e0 + i;
        float4 hv = make_float4(0.f, 0.f, 0.f, 0.f);
        if (n < N) hv = *(const float4*)(hin + (size_t)n * HD + f0);
        float x0 = fmaxf(v[i][0] + hv.x + bv.x, 0.f);
        float x1 = fmaxf(v[i][1] + hv.y + bv.y, 0.f);
        float x2 = fmaxf(v[i][2] + hv.z + bv.z, 0.f);
        float x3 = fmaxf(v[i][3] + hv.w + bv.w, 0.f);
        float s = x0 + x1 + x2 + x3;
        float s2 = x0 * x0 + x1 * x1 + x2 * x2 + x3 * x3;
#pragma unroll
        for (int o = 8; o; o >>= 1) {
            s  += __shfl_xor_sync(0xffffffffu, s, o);
            s2 += __shfl_xor_sync(0xffffffffu, s2, o);
        }
        float mean = s * 0.015625f;
        float var = fmaf(-mean, mean, s2 * 0.015625f);
        float rs = rsqrtf(var + LN_EPS);
        if (n < N) {
            float4 o4 = make_float4((x0 - mean) * rs * gv.x + btv.x,
                                    (x1 - mean) * rs * gv.y + btv.y,
                                    (x2 - mean) * rs * gv.z + btv.z,
                                    (x3 - mean) * rs * gv.w + btv.w);
            *(float4*)(g_h + (size_t)n * HD + f0) = o4;
        }
    }
}

// K4: per-graph sums (sorted graph_ids -> run-length flush, few atomics)
__global__ __launch_bounds__(512) void k_pool(const int* __restrict__ gid, int N) {
    int t = threadIdx.x;
    int f = t & 63;
    int sub = t >> 6;
    int base = blockIdx.x * 1024 + sub * 128;
    if (base >= N) return;
    int end = min(base + 128, N);
    int cur = gid[base];
    float sum = 0.f;
    for (int n = base; n < end; n++) {
        int g = gid[n];
        if (g != cur) { atomicAdd(&g_ctx[cur * HD + f], sum); sum = 0.f; cur = g; }
        sum += g_h[(size_t)n * HD + f];
    }
    atomicAdd(&g_ctx[cur * HD + f], sum);
}

// K5: divide by counts (binary search on sorted graph_ids)
__global__ void k_final(const int* __restrict__ gid, float* __restrict__ out, int N) {
    int t = threadIdx.x;  // 1024 threads = 16 graphs x 64 feats
    int g = t >> 6;
    int lo = 0, hi = N;
    while (lo < hi) { int m = (lo + hi) >> 1; if (gid[m] < g) lo = m + 1; else hi = m; }
    int lo2 = lo, hi2 = N;
    while (lo2 < hi2) { int m = (lo2 + hi2) >> 1; if (gid[m] < g + 1) lo2 = m + 1; else hi2 = m; }
    float c = (float)(hi2 - lo);
    out[t] = g_ctx[t] / fmaxf(c, 1.f);
}

extern "C" void kernel_launch(void* const* d_in, const int* in_sizes, int n_in,
                              void* d_out, int out_size) {
    const float* h0    = (const float*)d_in[0];
    const float* emb   = (const float*)d_in[1];
    const int*   esrc  = (const int*)d_in[2];
    const int*   etgt  = (const int*)d_in[3];
    const int*   gid   = (const int*)d_in[4];
    const float* Wmsg  = (const float*)d_in[5];
    const float* bmsg  = (const float*)d_in[6];
    const float* Wres  = (const float*)d_in[7];
    const float* bres  = (const float*)d_in[8];
    const float* gamma = (const float*)d_in[9];
    const float* beta  = (const float*)d_in[10];
    float* out = (float*)d_out;

    int N = in_sizes[0] / HD;
    int E = in_sizes[1] / HD;
    int nbN = (N + TILE - 1) / TILE;
    int nbE = (int)(((long long)E + ETILE - 1) / ETILE);

    // hop 0
    k_initP<<<nbN, 128>>>(h0, 0, Wmsg, bmsg, N, 1);
    k_edge_mma<<<nbE, 128>>>(emb, esrc, etgt, Wmsg + 4096, E);
    k_node<<<nbN, 128>>>(h0, 0, Wres, bres, gamma, beta, N);
    // hop 1
    k_initP<<<nbN, 128>>>(nullptr, 1, Wmsg + 8192, bmsg + 64, N, 0);
    k_edge_mma<<<nbE, 128>>>(emb, esrc, etgt, Wmsg + 8192 + 4096, E);
    k_node<<<nbN, 128>>>(nullptr, 1, Wres + 8192, bres + 64, gamma, beta, N);
    // pooling
    k_pool<<<(N + 1023) / 1024, 512>>>(gid, N);
    k_final<<<1, 1024>>>(gid, out, N);
}

// round 5
// speedup vs baseline: 1.0921x; 1.0921x over previous
#include <cuda_runtime.h>

#define HD 64
#define NG 16
#define TILE 32
#define ETILE 64
#define APAD 34
#define SST 68          // smem stride (floats/uints) for mma tiles: conflict-free
#define LN_EPS 1e-3f
#define NMAX 100000
#define EDGE_GRID 592   // 148 SMs x 4 resident CTAs
#define EDGE_SMEM (HD*SST*4 + 2*ETILE*SST*4 + 2*2*ETILE*4)

typedef unsigned long long u64;
typedef unsigned int uint;

// persistent scratch (device globals; allocation is forbidden)
__device__ float g_h[NMAX * HD];
__device__ float g_P[NMAX * HD];
__device__ float g_pool[NMAX * HD];
__device__ float g_ctx[NG * HD];

// ---------------- helpers ----------------
__device__ __forceinline__ u64 dup2(float x) {
    u64 r; unsigned xi = __float_as_uint(x);
    asm("mov.b64 %0, {%1, %1};" : "=l"(r) : "r"(xi));
    return r;
}
__device__ __forceinline__ float2 unpack2(u64 v) {
    unsigned lo, hi;
    asm("mov.b64 {%0, %1}, %2;" : "=r"(lo), "=r"(hi) : "l"(v));
    return make_float2(__uint_as_float(lo), __uint_as_float(hi));
}
__device__ __forceinline__ void ffma2(u64& d, u64 a, u64 b) {
    asm("fma.rn.f32x2 %0, %1, %2, %0;" : "+l"(d) : "l"(a), "l"(b));
}
__device__ __forceinline__ void redv2(float* p, float x, float y) {
    asm volatile("red.global.add.v2.f32 [%0], {%1,%2};"
                 :: "l"(p), "f"(x), "f"(y) : "memory");
}
__device__ __forceinline__ uint to_tf32(float f) {
    uint r; asm("cvt.rna.tf32.f32 %0, %1;" : "=r"(r) : "f"(f));
    return r;
}
__device__ __forceinline__ void mma_tf32(float c[4], uint a0, uint a1, uint a2, uint a3,
                                         uint b0, uint b1) {
    asm("mma.sync.aligned.m16n8k8.row.col.f32.tf32.tf32.f32 "
        "{%0,%1,%2,%3}, {%4,%5,%6,%7}, {%8,%9}, {%0,%1,%2,%3};"
        : "+f"(c[0]), "+f"(c[1]), "+f"(c[2]), "+f"(c[3])
        : "r"(a0), "r"(a1), "r"(a2), "r"(a3), "r"(b0), "r"(b1));
}
__device__ __forceinline__ void cpa16(uint dst, const void* src) {
    asm volatile("cp.async.ca.shared.global [%0], [%1], 16;" :: "r"(dst), "l"(src));
}

// ---------------- fp32 SIMT GEMM pieces (node-side kernels) ----------------
__device__ __forceinline__ void stage_w(const float* __restrict__ W, float* sW) {
    int t = threadIdx.x;
    float4* d4 = (float4*)sW;
    const float4* s4 = (const float4*)W;
#pragma unroll
    for (int i = 0; i < 8; i++) d4[t + i * 128] = s4[t + i * 128];
}
__device__ __forceinline__ void stage_xT(const float* __restrict__ X, float* sA, int valid) {
    int t = threadIdx.x;
#pragma unroll
    for (int i = 0; i < 4; i++) {
        int flat = 4 * t + 512 * i;
        int r = flat >> 6, k = flat & 63;
        float4 v = make_float4(0.f, 0.f, 0.f, 0.f);
        if (r < valid) v = *(const float4*)(X + flat);
        sA[(k + 0) * APAD + r] = v.x;
        sA[(k + 1) * APAD + r] = v.y;
        sA[(k + 2) * APAD + r] = v.z;
        sA[(k + 3) * APAD + r] = v.w;
    }
}
__device__ __forceinline__ void gemm_tile(const float* sA, const float* sW,
                                          int e0, int f0, u64 acc[2][4]) {
    const float* pA = sA + e0;
    const float* pW = sW + f0;
#pragma unroll 8
    for (int k = 0; k < 64; k++) {
        u64 a01 = *(const u64*)(pA);
        u64 a23 = *(const u64*)(pA + 2);
        float4 w = *(const float4*)(pW);
        u64 w0 = dup2(w.x), w1 = dup2(w.y), w2 = dup2(w.z), w3 = dup2(w.w);
        ffma2(acc[0][0], a01, w0); ffma2(acc[1][0], a23, w0);
        ffma2(acc[0][1], a01, w1); ffma2(acc[1][1], a23, w1);
        ffma2(acc[0][2], a01, w2); ffma2(acc[1][2], a23, w2);
        ffma2(acc[0][3], a01, w3); ffma2(acc[1][3], a23, w3);
        pA += APAD; pW += 64;
    }
}
__device__ __forceinline__ void acc_to_rows(u64 acc[2][4], float v[4][4]) {
#pragma unroll
    for (int p = 0; p < 2; p++)
#pragma unroll
        for (int j = 0; j < 4; j++) {
            float2 u = unpack2(acc[p][j]);
            v[2 * p][j] = u.x;
            v[2 * p + 1][j] = u.y;
        }
}

// K1: P = h @ W1 + b ; zero pooled ; (optionally) zero ctx
__global__ __launch_bounds__(128) void k_initP(
    const float* __restrict__ hext, int use_gh,
    const float* __restrict__ W1, const float* __restrict__ b,
    int N, int zero_ctx)
{
    __shared__ float sA[HD * APAD];
    __shared__ float sW[HD * HD];
    const float* hsrc = use_gh ? g_h : hext;
    int t = threadIdx.x;
    int nb = blockIdx.x * TILE;
    stage_xT(hsrc + (size_t)nb * HD, sA, min(TILE, N - nb));
    stage_w(W1, sW);
    __syncthreads();
    int e0 = (t >> 4) * 4, f0 = (t & 15) * 4;
    u64 acc[2][4] = {};
    gemm_tile(sA, sW, e0, f0, acc);
    float v[4][4]; acc_to_rows(acc, v);
    float4 bv = *(const float4*)(b + f0);
#pragma unroll
    for (int i = 0; i < 4; i++) {
        int n = nb + e0 + i;
        if (n < N)
            *(float4*)(g_P + (size_t)n * HD + f0) =
                make_float4(v[i][0] + bv.x, v[i][1] + bv.y, v[i][2] + bv.z, v[i][3] + bv.w);
    }
#pragma unroll
    for (int i = 0; i < 4; i++) {
        int flat = 4 * (t + 128 * i);
        int r = flat >> 6;
        if (nb + r < N)
            *(float4*)(g_pool + (size_t)nb * HD + flat) = make_float4(0.f, 0.f, 0.f, 0.f);
    }
    if (zero_ctx && blockIdx.x == 0)
        for (int i = t; i < NG * HD; i += 128) g_ctx[i] = 0.f;
}

// K2: persistent double-buffered cp.async edge kernel.
// msg = relu(P[src] + emb @ W2) ; pooled[tgt] += msg
__global__ __launch_bounds__(128) void k_edge_pipe(
    const float* __restrict__ emb, const int* __restrict__ esrc,
    const int* __restrict__ etgt, const float* __restrict__ W2, long long E)
{
    extern __shared__ uint dsm[];
    uint* sW  = dsm;                          // [HD * SST] tf32 (transposed [n][k])
    uint* sA  = dsm + HD * SST;               // [2][ETILE * SST] raw fp32 bits
    int*  sid = (int*)(dsm + HD * SST + 2 * ETILE * SST);  // [2][2*ETILE]

    int t = threadIdx.x;
    uint sA_base = (uint)__cvta_generic_to_shared(sA);

    // stage W2 transposed [n][k] as tf32 (once per block)
#pragma unroll
    for (int i = 0; i < 8; i++) {
        int flat = 4 * t + 512 * i;
        int k = flat >> 6, n = flat & 63;
        float4 v = *(const float4*)(W2 + flat);
        sW[(n + 0) * SST + k] = to_tf32(v.x);
        sW[(n + 1) * SST + k] = to_tf32(v.y);
        sW[(n + 2) * SST + k] = to_tf32(v.z);
        sW[(n + 3) * SST + k] = to_tf32(v.w);
    }

    int lane = t & 31;
    int gid4 = lane >> 2;
    int tig  = lane & 3;
    int r0   = (t >> 5) * 16;

    long long nt_total = (E + ETILE - 1) / ETILE;
    long long tile = blockIdx.x;
    int buf = 0;

    // prologue prefetch
    if (tile < nt_total) {
        long long eb = tile * ETILE;
#pragma unroll
        for (int i = 0; i < 8; i++) {
            int chunk = t + 128 * i;            // 0..1023
            int r = chunk >> 4, c = chunk & 15; // row, 16B-chunk in row
            long long row = eb + r; if (row >= E) row = E - 1;
            cpa16(sA_base + (uint)((r * SST + 4 * c) * 4), emb + row * HD + 4 * c);
        }
        if (t < ETILE) {
            long long e = eb + t;
            sid[t]         = (e < E) ? esrc[e] : 0;
            sid[ETILE + t] = (e < E) ? etgt[e] : 0;
        }
    }
    asm volatile("cp.async.commit_group;" ::: "memory");

    while (tile < nt_total) {
        long long nxt = tile + gridDim.x;
        // prefetch next tile into other buffer
        if (nxt < nt_total) {
            long long eb = nxt * ETILE;
            uint dbase = sA_base + (uint)((buf ^ 1) * ETILE * SST * 4);
#pragma unroll
            for (int i = 0; i < 8; i++) {
                int chunk = t + 128 * i;
                int r = chunk >> 4, c = chunk & 15;
                long long row = eb + r; if (row >= E) row = E - 1;
                cpa16(dbase + (uint)((r * SST + 4 * c) * 4), emb + row * HD + 4 * c);
            }
            if (t < ETILE) {
                long long e = eb + t;
                sid[(buf ^ 1) * 2 * ETILE + t]         = (e < E) ? esrc[e] : 0;
                sid[(buf ^ 1) * 2 * ETILE + ETILE + t] = (e < E) ? etgt[e] : 0;
            }
        }
        asm volatile("cp.async.commit_group;" ::: "memory");
        asm volatile("cp.async.wait_group 1;" ::: "memory");
        __syncthreads();

        // ---- compute current tile ----
        long long eb = tile * ETILE;
        const uint* A = sA + buf * ETILE * SST;
        const int* id = sid + buf * 2 * ETILE;

        float acc[8][4] = {};
        const uint* aRow0 = A + (r0 + gid4) * SST;
        const uint* aRow1 = aRow0 + 8 * SST;
#pragma unroll
        for (int kk = 0; kk < 8; kk++) {
            int ca = kk * 8 + tig;
            uint a0 = aRow0[ca], a1 = aRow1[ca], a2 = aRow0[ca + 4], a3 = aRow1[ca + 4];
#pragma unroll
            for (int nt = 0; nt < 8; nt++) {
                const uint* bp = sW + (nt * 8 + gid4) * SST + ca;
                mma_tf32(acc[nt], a0, a1, a2, a3, bp[0], bp[4]);
            }
        }

        // epilogue: relu(P[src] + acc) -> red.v2 to pool[tgt]
#pragma unroll
        for (int p = 0; p < 2; p++) {
            int row = r0 + gid4 + 8 * p;
            if (eb + row < E) {
                int s = id[row], g = id[ETILE + row];
                const float* Ps = g_P + (size_t)s * HD;
                float* Pg = g_pool + (size_t)g * HD;
#pragma unroll
                for (int nt = 0; nt < 8; nt++) {
                    int col = nt * 8 + 2 * tig;
                    float2 pv = *(const float2*)(Ps + col);
                    float m0 = fmaxf(acc[nt][2 * p + 0] + pv.x, 0.f);
                    float m1 = fmaxf(acc[nt][2 * p + 1] + pv.y, 0.f);
                    redv2(Pg + col, m0, m1);
                }
            }
        }
        __syncthreads();   // all reads of buf done before it is refilled next iter
        buf ^= 1;
        tile = nxt;
    }
}

// K3: h = LayerNorm(relu(h + h@Wres[0:64] + pooled@Wres[64:128] + b))
__global__ __launch_bounds__(128) void k_node(
    const float* __restrict__ hext, int use_gh,
    const float* __restrict__ Wres, const float* __restrict__ bres,
    const float* __restrict__ gam, const float* __restrict__ bet, int N)
{
    __shared__ float sA[HD * APAD];
    __shared__ float sW[HD * HD];
    const float* hin = use_gh ? g_h : hext;
    int t = threadIdx.x;
    int nb = blockIdx.x * TILE;
    int valid = min(TILE, N - nb);
    int e0 = (t >> 4) * 4, f0 = (t & 15) * 4;
    u64 acc[2][4] = {};

    stage_xT(hin + (size_t)nb * HD, sA, valid);
    stage_w(Wres, sW);
    __syncthreads();
    gemm_tile(sA, sW, e0, f0, acc);
    __syncthreads();
    stage_xT(g_pool + (size_t)nb * HD, sA, valid);
    stage_w(Wres + 4096, sW);
    __syncthreads();
    gemm_tile(sA, sW, e0, f0, acc);

    float v[4][4]; acc_to_rows(acc, v);
    float4 bv = *(const float4*)(bres + f0);
    float4 gv = *(const float4*)(gam + f0);
    float4 btv = *(const float4*)(bet + f0);
#pragma unroll
    for (int i = 0; i < 4; i++) {
        int n = nb + e0 + i;
        float4 hv = make_float4(0.f, 0.f, 0.f, 0.f);
        if (n < N) hv = *(const float4*)(hin + (size_t)n * HD + f0);
        float x0 = fmaxf(v[i][0] + hv.x + bv.x, 0.f);
        float x1 = fmaxf(v[i][1] + hv.y + bv.y, 0.f);
        float x2 = fmaxf(v[i][2] + hv.z + bv.z, 0.f);
        float x3 = fmaxf(v[i][3] + hv.w + bv.w, 0.f);
        float s = x0 + x1 + x2 + x3;
        float s2 = x0 * x0 + x1 * x1 + x2 * x2 + x3 * x3;
#pragma unroll
        for (int o = 8; o; o >>= 1) {
            s  += __shfl_xor_sync(0xffffffffu, s, o);
            s2 += __shfl_xor_sync(0xffffffffu, s2, o);
        }
        float mean = s * 0.015625f;
        float var = fmaf(-mean, mean, s2 * 0.015625f);
        float rs = rsqrtf(var + LN_EPS);
        if (n < N) {
            float4 o4 = make_float4((x0 - mean) * rs * gv.x + btv.x,
                                    (x1 - mean) * rs * gv.y + btv.y,
                                    (x2 - mean) * rs * gv.z + btv.z,
                                    (x3 - mean) * rs * gv.w + btv.w);
            *(float4*)(g_h + (size_t)n * HD + f0) = o4;
        }
    }
}

// K4: per-graph sums (sorted graph_ids -> run-length flush, few atomics)
__global__ __launch_bounds__(512) void k_pool(const int* __restrict__ gid, int N) {
    int t = threadIdx.x;
    int f = t & 63;
    int sub = t >> 6;
    int base = blockIdx.x * 1024 + sub * 128;
    if (base >= N) return;
    int end = min(base + 128, N);
    int cur = gid[base];
    float sum = 0.f;
    for (int n = base; n < end; n++) {
        int g = gid[n];
        if (g != cur) { atomicAdd(&g_ctx[cur * HD + f], sum); sum = 0.f; cur = g; }
        sum += g_h[(size_t)n * HD + f];
    }
    atomicAdd(&g_ctx[cur * HD + f], sum);
}

// K5: divide by counts (binary search on sorted graph_ids)
__global__ void k_final(const int* __restrict__ gid, float* __restrict__ out, int N) {
    int t = threadIdx.x;  // 1024 threads = 16 graphs x 64 feats
    int g = t >> 6;
    int lo = 0, hi = N;
    while (lo < hi) { int m = (lo + hi) >> 1; if (gid[m] < g) lo = m + 1; else hi = m; }
    int lo2 = lo, hi2 = N;
    while (lo2 < hi2) { int m = (lo2 + hi2) >> 1; if (gid[m] < g + 1) lo2 = m + 1; else hi2 = m; }
    float c = (float)(hi2 - lo);
    out[t] = g_ctx[t] / fmaxf(c, 1.f);
}

extern "C" void kernel_launch(void* const* d_in, const int* in_sizes, int n_in,
                              void* d_out, int out_size) {
    const float* h0    = (const float*)d_in[0];
    const float* emb   = (const float*)d_in[1];
    const int*   esrc  = (const int*)d_in[2];
    const int*   etgt  = (const int*)d_in[3];
    const int*   gid   = (const int*)d_in[4];
    const float* Wmsg  = (const float*)d_in[5];
    const float* bmsg  = (const float*)d_in[6];
    const float* Wres  = (const float*)d_in[7];
    const float* bres  = (const float*)d_in[8];
    const float* gamma = (const float*)d_in[9];
    const float* beta  = (const float*)d_in[10];
    float* out = (float*)d_out;

    int N = in_sizes[0] / HD;
    long long E = (long long)in_sizes[1] / HD;
    int nbN = (N + TILE - 1) / TILE;

    static int smem_set = 0;
    if (!smem_set) {
        cudaFuncSetAttribute(k_edge_pipe, cudaFuncAttributeMaxDynamicSharedMemorySize,
                             EDGE_SMEM);
        smem_set = 1;
    }

    // hop 0
    k_initP<<<nbN, 128>>>(h0, 0, Wmsg, bmsg, N, 1);
    k_edge_pipe<<<EDGE_GRID, 128, EDGE_SMEM>>>(emb, esrc, etgt, Wmsg + 4096, E);
    k_node<<<nbN, 128>>>(h0, 0, Wres, bres, gamma, beta, N);
    // hop 1
    k_initP<<<nbN, 128>>>(nullptr, 1, Wmsg + 8192, bmsg + 64, N, 0);
    k_edge_pipe<<<EDGE_GRID, 128, EDGE_SMEM>>>(emb, esrc, etgt, Wmsg + 8192 + 4096, E);
    k_node<<<nbN, 128>>>(nullptr, 1, Wres + 8192, bres + 64, gamma, beta, N);
    // pooling
    k_pool<<<(N + 1023) / 1024, 512>>>(gid, N);
    k_final<<<1, 1024>>>(gid, out, N);
}